// round 8
// baseline (speedup 1.0000x reference)
#include <cuda_runtime.h>
#include <math.h>
#include <stdint.h>

#define BB 16
#define CC 3
#define TT 32
#define HH 224
#define WW 224
#define GS 32
#define GH 7
#define GW 7
#define NPF 49
#define NODES 1568
#define NPATCH 25088
#define NPP 3072
#define NEDGE 15962
#define XFLOATS 250880
#define CAPL 18            // slots per lane per window
#define SUBCAP 64
#define PPB 4              // patches (warps) per block

// global pivots for N(0,1) patch data: windows around q25 / med / q75
#define B0 (-0.77448975f)
#define B1 (-0.57448975f)
#define B2 (-0.10f)
#define B3 ( 0.10f)
#define B4 ( 0.57448975f)
#define B5 ( 0.77448975f)

__device__ __forceinline__ float wsumf(float x) {
    #pragma unroll
    for (int o = 16; o; o >>= 1) x += __shfl_xor_sync(0xffffffffu, x, o);
    return x;
}
__device__ __forceinline__ int wsumi(int x) {
    #pragma unroll
    for (int o = 16; o; o >>= 1) x += __shfl_xor_sync(0xffffffffu, x, o);
    return x;
}
__device__ __forceinline__ float wminf(float x) {
    #pragma unroll
    for (int o = 16; o; o >>= 1) x = fminf(x, __shfl_xor_sync(0xffffffffu, x, o));
    return x;
}
__device__ __forceinline__ float wmaxf(float x) {
    #pragma unroll
    for (int o = 16; o; o >>= 1) x = fmaxf(x, __shfl_xor_sync(0xffffffffu, x, o));
    return x;
}

__device__ __forceinline__ uint32_t xform(float f) {
    uint32_t u = __float_as_uint(f);
    return (u & 0x80000000u) ? ~u : (u | 0x80000000u);
}
__device__ __forceinline__ float unxform(uint32_t u) {
    u = (u & 0x80000000u) ? (u ^ 0x80000000u) : ~u;
    return __uint_as_float(u);
}

// packed f32x2 helpers
__device__ __forceinline__ uint64_t pk2(float a, float b) {
    uint64_t r; asm("mov.b64 %0,{%1,%2};" : "=l"(r) : "f"(a), "f"(b)); return r;
}
__device__ __forceinline__ void upk2(uint64_t p, float& a, float& b) {
    asm("mov.b64 {%0,%1},%2;" : "=f"(a), "=f"(b) : "l"(p));
}
__device__ __forceinline__ uint64_t add2(uint64_t a, uint64_t b) {
    uint64_t r; asm("add.rn.f32x2 %0,%1,%2;" : "=l"(r) : "l"(a), "l"(b)); return r;
}
__device__ __forceinline__ uint64_t mul2(uint64_t a, uint64_t b) {
    uint64_t r; asm("mul.rn.f32x2 %0,%1,%2;" : "=l"(r) : "l"(a), "l"(b)); return r;
}
__device__ __forceinline__ uint64_t fma2(uint64_t a, uint64_t b, uint64_t c) {
    uint64_t r; asm("fma.rn.f32x2 %0,%1,%2,%3;" : "=l"(r) : "l"(a), "l"(b), "l"(c)); return r;
}

// exact count of xform(x) <= code over the patch (gmem reload)
__device__ int count_le_code(const float* __restrict__ v, int b, int t, int i, int j,
                             int lane, uint32_t code) {
    const int sub = lane & 7, rg = lane >> 3;
    int c = 0;
    #pragma unroll 4
    for (int k = 0; k < 24; k++) {
        int r = k * 4 + rg;
        int ch = r >> 5, y = r & 31;
        size_t base = ((((size_t)b * CC + ch) * TT + t) * HH + (size_t)(i * GS + y)) * WW
                      + (size_t)(j * GS) + (size_t)(sub * 4);
        float4 x4 = *reinterpret_cast<const float4*>(v + base);
        c += (xform(x4.x) <= code) + (xform(x4.y) <= code)
           + (xform(x4.z) <= code) + (xform(x4.w) <= code);
    }
    return wsumi(c);
}

// guaranteed-exact rank select by bisection over float code space (rare path)
__device__ float slow_rank(const float* __restrict__ v, int b, int t, int i, int j,
                           int lane, int r) {
    uint32_t lo = 0u, hi = 0xFFFFFFFFu;
    while (lo < hi) {
        uint32_t mid = lo + ((hi - lo) >> 1);
        int c = count_le_code(v, b, t, i, j, lane, mid);
        if (c >= r + 1) hi = mid; else lo = mid + 1;
    }
    return unxform(lo);
}

// exact tie-aware select of two ranks in compact sub[0..cnt), broadcast result
__device__ __forceinline__ void select2c(const float* sub, int cnt, int rr0, int rr1,
                                         int lane, float* o0, float* o1) {
    float a0 = 0.f, a1 = 0.f;
    bool f0 = false, f1 = false;
    for (int base = 0; base < cnt; base += 32) {
        int idx = base + lane;
        float key = (idx < cnt) ? sub[idx] : 0.f;
        int less = 0, eq = 0;
        for (int m = 0; m < cnt; m++) {
            float c = sub[m];
            less += (c < key);
            eq   += (c == key);
        }
        if (idx < cnt) {
            if (rr0 >= less && rr0 < less + eq) { a0 = key; f0 = true; }
            if (rr1 >= less && rr1 < less + eq) { a1 = key; f1 = true; }
        }
    }
    unsigned m0 = __ballot_sync(0xffffffffu, f0);
    unsigned m1 = __ballot_sync(0xffffffffu, f1);
    int s0 = m0 ? (__ffs(m0) - 1) : 0;
    int s1 = m1 ? (__ffs(m1) - 1) : 0;
    *o0 = __shfl_sync(0xffffffffu, a0, s0);
    *o1 = __shfl_sync(0xffffffffu, a1, s1);
}

__global__ void __launch_bounds__(32 * PPB)
feat_kernel(const float* __restrict__ v, float* __restrict__ out)
{
    // buf layout: [patch][window][slot][lane] -> bank == lane, conflict-free
    __shared__ float buf[PPB][3][CAPL][32];
    __shared__ float subb[PPB][SUBCAP];

    const int lane = threadIdx.x & 31;
    const int warp = threadIdx.x >> 5;
    const int p = blockIdx.x * PPB + warp;
    const int j = p % GW;
    int tmp = p / GW;
    const int i = tmp % GH;
    tmp /= GH;
    const int t = tmp % TT;
    const int b = tmp / TT;

    const int sub = lane & 7, rg = lane >> 3;

    // ---- single fused gmem pass ----
    uint64_t S1p = 0, S2p = 0, S3p = 0, S4p = 0;   // packed f32x2 accumulators (0.0f pair)
    float mn = INFINITY, mx = -INFINITY;
    int a0 = 0, a1 = 0, a2 = 0;       // counts below B0/B2/B4
    int h0 = 0, h1 = 0, h2 = 0;       // in-window hit counts (per lane)

    #pragma unroll 4
    for (int k = 0; k < 24; k++) {
        int r = k * 4 + rg;
        int ch = r >> 5, y = r & 31;
        size_t base = ((((size_t)b * CC + ch) * TT + t) * HH + (size_t)(i * GS + y)) * WW
                      + (size_t)(j * GS) + (size_t)(sub * 4);
        float4 x4 = *reinterpret_cast<const float4*>(v + base);

        // moments on packed pairs
        uint64_t pA = pk2(x4.x, x4.y), pB = pk2(x4.z, x4.w);
        S1p = add2(S1p, pA);
        uint64_t qA = mul2(pA, pA);
        S2p = add2(S2p, qA);
        S3p = fma2(qA, pA, S3p);
        S4p = fma2(qA, qA, S4p);
        S1p = add2(S1p, pB);
        uint64_t qB = mul2(pB, pB);
        S2p = add2(S2p, qB);
        S3p = fma2(qB, pB, S3p);
        S4p = fma2(qB, qB, S4p);

        float xs[4] = {x4.x, x4.y, x4.z, x4.w};
        #pragma unroll
        for (int e = 0; e < 4; e++) {
            float x = xs[e];
            mn = fminf(mn, x);
            mx = fmaxf(mx, x);
            bool p0 = x < B0, p1 = x < B1, p2 = x < B2,
                 p3 = x < B3, p4 = x < B4, p5 = x < B5;
            a0 += p0; a1 += p2; a2 += p4;
            bool i0 = (!p0) && p1, i1 = (!p2) && p3, i2 = (!p4) && p5;
            if (i0) { if (h0 < CAPL) buf[warp][0][h0][lane] = x; h0++; }
            if (i1) { if (h1 < CAPL) buf[warp][1][h1][lane] = x; h1++; }
            if (i2) { if (h2 < CAPL) buf[warp][2][h2][lane] = x; h2++; }
        }
    }

    // ---- reductions ----
    float s1a, s1b, s2a, s2b, s3a, s3b, s4a, s4b;
    upk2(S1p, s1a, s1b); upk2(S2p, s2a, s2b);
    upk2(S3p, s3a, s3b); upk2(S4p, s4a, s4b);
    float S1 = wsumf(s1a + s1b), S2 = wsumf(s2a + s2b);
    float S3 = wsumf(s3a + s3b), S4 = wsumf(s4a + s4b);
    mn = wminf(mn); mx = wmaxf(mx);
    int ovf = (h0 > CAPL) | (h1 > CAPL) | (h2 > CAPL);
    ovf = __ballot_sync(0xffffffffu, ovf) != 0;
    int clo[3], g[3];
    clo[0] = wsumi(a0); clo[1] = wsumi(a1); clo[2] = wsumi(a2);
    g[0] = wsumi(h0); g[1] = wsumi(h1); g[2] = wsumi(h2);
    int myh[3] = { h0 < CAPL ? h0 : CAPL, h1 < CAPL ? h1 : CAPL, h2 < CAPL ? h2 : CAPL };
    __syncwarp();

    // ---- per-window refine + exact select ----
    const float Blo[3] = {B0, B2, B4}, Bhi[3] = {B1, B3, B5};
    const int RMIN[3] = {767, 1535, 2303}, RMAX[3] = {768, 1535, 2304};
    float ql[3], qh[3];
    const unsigned ltm = (1u << lane) - 1u;

    #pragma unroll
    for (int w = 0; w < 3; w++) {
        int rmin = RMIN[w], rmax = RMAX[w];
        bool winok = (!ovf) && (clo[w] <= rmin) && (rmax < clo[w] + g[w]);
        bool done = false;
        if (winok) {
            float wspan = Bhi[w] - Blo[w];
            float inv_g = 1.0f / (float)g[w];
            float p_lo = fmaxf(Blo[w], Blo[w] + ((float)(rmin - 26 - clo[w])) * inv_g * wspan);
            float p_hi = fminf(Bhi[w], Blo[w] + ((float)(rmax + 28 - clo[w])) * inv_g * wspan);

            int sc = 0, elo = 0;
            int mh = myh[w];
            #pragma unroll
            for (int s = 0; s < CAPL; s++) {
                bool act = s < mh;
                float x = buf[warp][w][s][lane];
                elo += act && (x < p_lo);
                bool g2 = act && (x >= p_lo) && (x < p_hi);
                unsigned mk = __ballot_sync(0xffffffffu, g2);
                if (g2) {
                    int pos = sc + __popc(mk & ltm);
                    if (pos < SUBCAP) subb[warp][pos] = x;
                }
                sc += __popc(mk);
            }
            elo = wsumi(elo);
            __syncwarp();
            int base = clo[w] + elo;
            if (sc <= SUBCAP && base <= rmin && rmax < base + sc) {
                float r0, r1;
                select2c(subb[warp], sc, rmin - base, rmax - base, lane, &r0, &r1);
                ql[w] = r0; qh[w] = r1;
                done = true;
            }
            __syncwarp();
        }
        if (!done) {
            ql[w] = slow_rank(v, b, t, i, j, lane, rmin);
            qh[w] = (rmax == rmin) ? ql[w] : slow_rank(v, b, t, i, j, lane, rmax);
        }
    }

    if (lane == 0) {
        const double n = (double)NPP;
        double s1 = S1, s2 = S2, s3 = S3, s4 = S4;
        double mean = s1 / n;
        double c2 = s2 - n * mean * mean;
        double c3 = s3 - 3.0 * mean * s2 + 2.0 * n * mean * mean * mean;
        double m2s = mean * mean;
        double c4 = s4 - 4.0 * mean * s3 + 6.0 * m2s * s2 - 3.0 * n * m2s * m2s;
        double sd = sqrt(c2 / (n - 1.0));
        double sde = sd + 1e-8;
        double energy = s2 / n;
        double rms = sqrt(energy + 1e-8);
        double i3 = 1.0 / (sde * sde * sde);
        double skew = (c3 / n) * i3;
        double kurt = (c4 / n) * i3 / sde - 3.0;
        float q25 = ql[0] * 0.25f + qh[0] * 0.75f;
        float q75 = ql[2] * 0.75f + qh[2] * 0.25f;

        float* o = out + (size_t)p * 10;
        o[0] = (float)mean; o[1] = (float)sd; o[2] = mn; o[3] = mx;
        o[4] = (float)energy; o[5] = (float)rms; o[6] = (float)skew;
        o[7] = (float)kurt; o[8] = ql[1]; o[9] = q75 - q25;
    }
}

__device__ __forceinline__ int tau_t(int t) {
    int c = 0;
    if (t + 1 < TT) c++;
    if (t - 1 >= 0) c++;
    if (t + 2 < TT) c++;
    if (t - 2 >= 0) c++;
    return c;
}

__global__ void edge_kernel(float* __restrict__ out)
{
    int node = blockIdx.x * blockDim.x + threadIdx.x;
    if (node >= NODES) return;
    int t = node / NPF;
    int rem = node % NPF;
    int i = rem / GW;
    int j = rem % GW;

    int mt = t < 30 ? t : 30;
    int cum_tau = (t > 0 ? 2 : 0) + (t > 1 ? 3 : 0)
                + 4 * (mt > 2 ? (mt - 2) : 0) + (t > 30 ? 3 : 0);
    int taut = tau_t(t);
    int rowpref = (i == 0) ? 0 : (31 + 50 * (i - 1));
    int ci = (i == 0 || i == GH - 1) ? 2 : 3;
    int cumcj = (j > 0 ? 2 : 0) + 3 * (j > 1 ? (j - 1) : 0);
    int sp = rowpref + ci * cumcj - j;
    int off = 312 * t + 49 * cum_tau + sp + rem * taut;

    const int di[8] = {-1,-1,-1, 0, 0, 1, 1, 1};
    const int dj[8] = {-1, 0, 1,-1, 1,-1, 0, 1};
    int e = off;
    float fnode = (float)node;
    #pragma unroll
    for (int q = 0; q < 8; q++) {
        int ni = i + di[q], nj = j + dj[q];
        if (ni >= 0 && ni < GH && nj >= 0 && nj < GW) {
            out[e]         = fnode;
            out[NEDGE + e] = (float)(t * NPF + ni * GW + nj);
            e++;
        }
    }
    const int dts[4] = {1, -1, 2, -2};
    #pragma unroll
    for (int q = 0; q < 4; q++) {
        int tt2 = t + dts[q];
        if (tt2 >= 0 && tt2 < TT) {
            out[e]         = fnode;
            out[NEDGE + e] = (float)(tt2 * NPF + i * GW + j);
            e++;
        }
    }
}

extern "C" void kernel_launch(void* const* d_in, const int* in_sizes, int n_in,
                              void* d_out, int out_size)
{
    const float* video = (const float*)d_in[0];
    float* out = (float*)d_out;

    if (out_size >= XFLOATS + 2 * NEDGE) {
        edge_kernel<<<(NODES + 255) / 256, 256>>>(out + XFLOATS);
    }
    feat_kernel<<<NPATCH / PPB, 32 * PPB>>>(video, out);
}

// round 9
// speedup vs baseline: 1.3297x; 1.3297x over previous
#include <cuda_runtime.h>
#include <math.h>
#include <stdint.h>

#define BB 16
#define CC 3
#define TT 32
#define HH 224
#define WW 224
#define GS 32
#define GH 7
#define GW 7
#define NPF 49
#define NODES 1568
#define NPATCH 25088
#define NPP 3072
#define NEDGE 15962
#define XFLOATS 250880
#define CAP 96
#define PPB 4
#define GUARD 12.0f

// anchors (global pivots for N(0,1)-ish data)
#define A0 (-0.77448975f)
#define A1 (-0.10f)
#define A2 ( 0.57448975f)

__device__ __forceinline__ float wsumf(float x) {
    #pragma unroll
    for (int o = 16; o; o >>= 1) x += __shfl_xor_sync(0xffffffffu, x, o);
    return x;
}
__device__ __forceinline__ int wsumi(int x) {
    #pragma unroll
    for (int o = 16; o; o >>= 1) x += __shfl_xor_sync(0xffffffffu, x, o);
    return x;
}
__device__ __forceinline__ float wminf(float x) {
    #pragma unroll
    for (int o = 16; o; o >>= 1) x = fminf(x, __shfl_xor_sync(0xffffffffu, x, o));
    return x;
}
__device__ __forceinline__ float wmaxf(float x) {
    #pragma unroll
    for (int o = 16; o; o >>= 1) x = fmaxf(x, __shfl_xor_sync(0xffffffffu, x, o));
    return x;
}

__device__ __forceinline__ uint32_t xform(float f) {
    uint32_t u = __float_as_uint(f);
    return (u & 0x80000000u) ? ~u : (u | 0x80000000u);
}
__device__ __forceinline__ float unxform(uint32_t u) {
    u = (u & 0x80000000u) ? (u ^ 0x80000000u) : ~u;
    return __uint_as_float(u);
}

// exact count of xform(x) <= code over the patch (gmem)
__device__ __noinline__ int count_le_code(const float* __restrict__ v, int b, int t,
                                          int i, int j, int lane, uint32_t code) {
    const int sub = lane & 7, rg = lane >> 3;
    int c = 0;
    for (int k = 0; k < 24; k++) {
        int r = k * 4 + rg;
        int ch = r >> 5, y = r & 31;
        size_t base = ((((size_t)b * CC + ch) * TT + t) * HH + (size_t)(i * GS + y)) * WW
                      + (size_t)(j * GS) + (size_t)(sub * 4);
        float4 x4 = *reinterpret_cast<const float4*>(v + base);
        c += (xform(x4.x) <= code) + (xform(x4.y) <= code)
           + (xform(x4.z) <= code) + (xform(x4.w) <= code);
    }
    return wsumi(c);
}

// guaranteed-exact rank select by bisection over float code space (rare path)
__device__ __noinline__ float slow_rank(const float* __restrict__ v, int b, int t,
                                        int i, int j, int lane, int r) {
    uint32_t lo = 0u, hi = 0xFFFFFFFFu;
    while (lo < hi) {
        uint32_t mid = lo + ((hi - lo) >> 1);
        int c = count_le_code(v, b, t, i, j, lane, mid);
        if (c >= r + 1) hi = mid; else lo = mid + 1;
    }
    return unxform(lo);
}

// exact tie-aware select of two ranks in buf[0..cnt), broadcast result
__device__ __forceinline__ void select2c(const float* buf, int cnt, int rr0, int rr1,
                                         int lane, float* o0, float* o1) {
    float a0 = 0.f, a1 = 0.f;
    bool f0 = false, f1 = false;
    for (int base = 0; base < cnt; base += 32) {
        int idx = base + lane;
        float key = (idx < cnt) ? buf[idx] : 0.f;
        int less = 0, eq = 0;
        for (int m = 0; m < cnt; m++) {
            float c = buf[m];
            less += (c < key);
            eq   += (c == key);
        }
        if (idx < cnt) {
            if (rr0 >= less && rr0 < less + eq) { a0 = key; f0 = true; }
            if (rr1 >= less && rr1 < less + eq) { a1 = key; f1 = true; }
        }
    }
    unsigned m0 = __ballot_sync(0xffffffffu, f0);
    unsigned m1 = __ballot_sync(0xffffffffu, f1);
    int s0 = m0 ? (__ffs(m0) - 1) : 0;
    int s1 = m1 ? (__ffs(m1) - 1) : 0;
    *o0 = __shfl_sync(0xffffffffu, a0, s0);
    *o1 = __shfl_sync(0xffffffffu, a1, s1);
}

__global__ void __launch_bounds__(32 * PPB)
feat_kernel(const float* __restrict__ v, float* __restrict__ out)
{
    __shared__ float cbuf[PPB][3][CAP];
    __shared__ int   dcur[PPB][3];

    const int lane = threadIdx.x & 31;
    const int warp = threadIdx.x >> 5;
    const int p = blockIdx.x * PPB + warp;
    const int j = p % GW;
    int tmp = p / GW;
    const int i = tmp % GH;
    tmp /= GH;
    const int t = tmp % TT;
    const int b = tmp / TT;

    const int sub = lane & 7, rg = lane >> 3;

    if (lane < 3) dcur[warp][lane] = 0;

    // ---- pass 1: moments + min/max + exact counts below 3 anchors ----
    float S1 = 0.f, S2 = 0.f, S3 = 0.f, S4 = 0.f;
    float mn = INFINITY, mx = -INFINITY;
    int a0 = 0, a1 = 0, a2 = 0;
    #pragma unroll 4
    for (int k = 0; k < 24; k++) {
        int r = k * 4 + rg;
        int ch = r >> 5, y = r & 31;
        size_t base = ((((size_t)b * CC + ch) * TT + t) * HH + (size_t)(i * GS + y)) * WW
                      + (size_t)(j * GS) + (size_t)(sub * 4);
        float4 x4 = *reinterpret_cast<const float4*>(v + base);
        float xs[4] = {x4.x, x4.y, x4.z, x4.w};
        #pragma unroll
        for (int e = 0; e < 4; e++) {
            float x = xs[e];
            float x2 = x * x;
            S1 += x; S2 += x2;
            S3 = fmaf(x2, x, S3);
            S4 = fmaf(x2, x2, S4);
            mn = fminf(mn, x);
            mx = fmaxf(mx, x);
            a0 += (x < A0); a1 += (x < A1); a2 += (x < A2);
        }
    }
    S1 = wsumf(S1); S2 = wsumf(S2); S3 = wsumf(S3); S4 = wsumf(S4);
    mn = wminf(mn); mx = wmaxf(mx);
    int a01 = wsumi(a0 | (a1 << 16));
    a2 = wsumi(a2);
    a0 = a01 & 0xFFFF; a1 = a01 >> 16;

    const float meanf = S1 * (1.0f / (float)NPP);
    const float sdf = sqrtf(fmaxf((S2 - (float)NPP * meanf * meanf) / ((float)NPP - 1.f), 0.f));

    float ql[3], qh[3];
    if (mx == mn) {
        ql[0] = qh[0] = ql[1] = qh[1] = ql[2] = qh[2] = mn;
    } else {
        // ---- analytic window placement from exact anchor counts ----
        const float AV[3]   = {A0, A1, A2};
        const int   CLOA[3] = {a0, a1, a2};
        const int   RMIN[3] = {767, 1535, 2303};
        const int   RMAX[3] = {768, 1535, 2304};
        const float FLO[3]  = {0.345f, 0.42f, 0.345f};   // >= local density (safe lo)
        const float FHI[3]  = {0.295f, 0.365f, 0.295f};  // <= local density (safe hi)
        float plo[3], phi[3];
        #pragma unroll
        for (int w = 0; w < 3; w++) {
            float dl = (float)RMIN[w] - GUARD - (float)CLOA[w];
            float dh = (float)RMAX[w] + GUARD - (float)CLOA[w];
            float denl = (dl >= 0.f) ? FLO[w] : FHI[w];
            float denh = (dh >= 0.f) ? FHI[w] : FLO[w];
            plo[w] = AV[w] + dl * sdf / ((float)NPP * denl);
            phi[w] = AV[w] + dh * sdf / ((float)NPP * denh);
        }
        __syncwarp();

        // ---- pass 2: re-read gmem; count below plo + atomic gather windows ----
        int c0 = 0, c1 = 0, c2 = 0;
        #pragma unroll 4
        for (int k = 0; k < 24; k++) {
            int r = k * 4 + rg;
            int ch = r >> 5, y = r & 31;
            size_t base = ((((size_t)b * CC + ch) * TT + t) * HH + (size_t)(i * GS + y)) * WW
                          + (size_t)(j * GS) + (size_t)(sub * 4);
            float4 x4 = *reinterpret_cast<const float4*>(v + base);
            float xs[4] = {x4.x, x4.y, x4.z, x4.w};
            #pragma unroll
            for (int e = 0; e < 4; e++) {
                float x = xs[e];
                bool l0 = x < plo[0]; c0 += l0;
                if (!l0 && x < phi[0]) {
                    int pos = atomicAdd(&dcur[warp][0], 1);
                    if (pos < CAP) cbuf[warp][0][pos] = x;
                }
                bool l1 = x < plo[1]; c1 += l1;
                if (!l1 && x < phi[1]) {
                    int pos = atomicAdd(&dcur[warp][1], 1);
                    if (pos < CAP) cbuf[warp][1][pos] = x;
                }
                bool l2 = x < plo[2]; c2 += l2;
                if (!l2 && x < phi[2]) {
                    int pos = atomicAdd(&dcur[warp][2], 1);
                    if (pos < CAP) cbuf[warp][2][pos] = x;
                }
            }
        }
        int c01 = wsumi(c0 | (c1 << 16));
        c2 = wsumi(c2);
        int cl[3] = {c01 & 0xFFFF, c01 >> 16, c2};
        __syncwarp();

        #pragma unroll
        for (int w = 0; w < 3; w++) {
            int g = dcur[warp][w];
            if (g <= CAP && cl[w] <= RMIN[w] && RMAX[w] < cl[w] + g) {
                select2c(cbuf[warp][w], g, RMIN[w] - cl[w], RMAX[w] - cl[w],
                         lane, &ql[w], &qh[w]);
            } else {
                ql[w] = slow_rank(v, b, t, i, j, lane, RMIN[w]);
                qh[w] = (RMAX[w] == RMIN[w]) ? ql[w]
                        : slow_rank(v, b, t, i, j, lane, RMAX[w]);
            }
        }
    }

    if (lane == 0) {
        const double n = (double)NPP;
        double s1 = S1, s2 = S2, s3 = S3, s4 = S4;
        double mean = s1 / n;
        double c2m = s2 - n * mean * mean;
        double c3m = s3 - 3.0 * mean * s2 + 2.0 * n * mean * mean * mean;
        double m2s = mean * mean;
        double c4m = s4 - 4.0 * mean * s3 + 6.0 * m2s * s2 - 3.0 * n * m2s * m2s;
        double sd = sqrt(c2m / (n - 1.0));
        double sde = sd + 1e-8;
        double energy = s2 / n;
        double rms = sqrt(energy + 1e-8);
        double i3 = 1.0 / (sde * sde * sde);
        double skew = (c3m / n) * i3;
        double kurt = (c4m / n) * i3 / sde - 3.0;
        float q25 = ql[0] * 0.25f + qh[0] * 0.75f;
        float q75 = ql[2] * 0.75f + qh[2] * 0.25f;

        float* o = out + (size_t)p * 10;
        o[0] = (float)mean; o[1] = (float)sd; o[2] = mn; o[3] = mx;
        o[4] = (float)energy; o[5] = (float)rms; o[6] = (float)skew;
        o[7] = (float)kurt; o[8] = ql[1]; o[9] = q75 - q25;
    }
}

__device__ __forceinline__ int tau_t(int t) {
    int c = 0;
    if (t + 1 < TT) c++;
    if (t - 1 >= 0) c++;
    if (t + 2 < TT) c++;
    if (t - 2 >= 0) c++;
    return c;
}

__global__ void edge_kernel(float* __restrict__ out)
{
    int node = blockIdx.x * blockDim.x + threadIdx.x;
    if (node >= NODES) return;
    int t = node / NPF;
    int rem = node % NPF;
    int i = rem / GW;
    int j = rem % GW;

    int mt = t < 30 ? t : 30;
    int cum_tau = (t > 0 ? 2 : 0) + (t > 1 ? 3 : 0)
                + 4 * (mt > 2 ? (mt - 2) : 0) + (t > 30 ? 3 : 0);
    int taut = tau_t(t);
    int rowpref = (i == 0) ? 0 : (31 + 50 * (i - 1));
    int ci = (i == 0 || i == GH - 1) ? 2 : 3;
    int cumcj = (j > 0 ? 2 : 0) + 3 * (j > 1 ? (j - 1) : 0);
    int sp = rowpref + ci * cumcj - j;
    int off = 312 * t + 49 * cum_tau + sp + rem * taut;

    const int di[8] = {-1,-1,-1, 0, 0, 1, 1, 1};
    const int dj[8] = {-1, 0, 1,-1, 1,-1, 0, 1};
    int e = off;
    float fnode = (float)node;
    #pragma unroll
    for (int q = 0; q < 8; q++) {
        int ni = i + di[q], nj = j + dj[q];
        if (ni >= 0 && ni < GH && nj >= 0 && nj < GW) {
            out[e]         = fnode;
            out[NEDGE + e] = (float)(t * NPF + ni * GW + nj);
            e++;
        }
    }
    const int dts[4] = {1, -1, 2, -2};
    #pragma unroll
    for (int q = 0; q < 4; q++) {
        int tt2 = t + dts[q];
        if (tt2 >= 0 && tt2 < TT) {
            out[e]         = fnode;
            out[NEDGE + e] = (float)(tt2 * NPF + i * GW + j);
            e++;
        }
    }
}

extern "C" void kernel_launch(void* const* d_in, const int* in_sizes, int n_in,
                              void* d_out, int out_size)
{
    const float* video = (const float*)d_in[0];
    float* out = (float*)d_out;

    if (out_size >= XFLOATS + 2 * NEDGE) {
        edge_kernel<<<(NODES + 255) / 256, 256>>>(out + XFLOATS);
    }
    feat_kernel<<<NPATCH / PPB, 32 * PPB>>>(video, out);
}

// round 10
// speedup vs baseline: 3.1538x; 2.3718x over previous
#include <cuda_runtime.h>
#include <math.h>
#include <stdint.h>

#define BB 16
#define CC 3
#define TT 32
#define HH 224
#define WW 224
#define GS 32
#define GH 7
#define GW 7
#define NPF 49
#define NODES 1568
#define NPATCH 25088
#define NPP 3072
#define NEDGE 15962
#define XFLOATS 250880
#define CAP 384
#define PPB 4
#define GUARD 26.0f
#define CHS 1605632u     // channel stride in elements (32*224*224)

__device__ __forceinline__ float wsumf(float x) {
    #pragma unroll
    for (int o = 16; o; o >>= 1) x += __shfl_xor_sync(0xffffffffu, x, o);
    return x;
}
__device__ __forceinline__ int wsumi(int x) {
    #pragma unroll
    for (int o = 16; o; o >>= 1) x += __shfl_xor_sync(0xffffffffu, x, o);
    return x;
}
__device__ __forceinline__ float wminf(float x) {
    #pragma unroll
    for (int o = 16; o; o >>= 1) x = fminf(x, __shfl_xor_sync(0xffffffffu, x, o));
    return x;
}
__device__ __forceinline__ float wmaxf(float x) {
    #pragma unroll
    for (int o = 16; o; o >>= 1) x = fmaxf(x, __shfl_xor_sync(0xffffffffu, x, o));
    return x;
}

__device__ __forceinline__ uint32_t xform(float f) {
    uint32_t u = __float_as_uint(f);
    return (u & 0x80000000u) ? ~u : (u | 0x80000000u);
}
__device__ __forceinline__ float unxform(uint32_t u) {
    u = (u & 0x80000000u) ? (u ^ 0x80000000u) : ~u;
    return __uint_as_float(u);
}

// exact count of xform(x) <= code over the patch (gmem; cold path)
__device__ __noinline__ int count_le_code(const float* __restrict__ v, uint32_t base0,
                                          int rg, int sub, uint32_t code) {
    int c = 0;
    for (int k = 0; k < 24; k++) {
        int r = k * 4 + rg;
        uint32_t idx = base0 + (uint32_t)(r >> 5) * CHS + (uint32_t)(r & 31) * 224u;
        float4 x4 = *reinterpret_cast<const float4*>(v + idx);
        c += (xform(x4.x) <= code) + (xform(x4.y) <= code)
           + (xform(x4.z) <= code) + (xform(x4.w) <= code);
    }
    return wsumi(c);
}

// guaranteed-exact rank select via bisection over float code space (cold path)
__device__ __noinline__ float slow_rank(const float* __restrict__ v, uint32_t base0,
                                        int rg, int sub, int r) {
    uint32_t lo = 0u, hi = 0xFFFFFFFFu;
    while (lo < hi) {
        uint32_t mid = lo + ((hi - lo) >> 1);
        int c = count_le_code(v, base0, rg, sub, mid);
        if (c >= r + 1) hi = mid; else lo = mid + 1;
    }
    return unxform(lo);
}

// one-pass window gather (cold path): count below lo + atomic-append members of [lo,hi)
__device__ __noinline__ int gather_window(const float* __restrict__ v, uint32_t base0,
                                          int rg, int sub, int lane, float lo, float hi,
                                          float* buf, int* ctr) {
    if (lane == 0) *ctr = 0;
    __syncwarp();
    int cl = 0;
    for (int k = 0; k < 24; k++) {
        int r = k * 4 + rg;
        uint32_t idx = base0 + (uint32_t)(r >> 5) * CHS + (uint32_t)(r & 31) * 224u;
        float4 x4 = *reinterpret_cast<const float4*>(v + idx);
        float xs[4] = {x4.x, x4.y, x4.z, x4.w};
        #pragma unroll
        for (int e = 0; e < 4; e++) {
            float x = xs[e];
            bool l = x < lo;
            cl += l;
            if (!l && x < hi) {
                int pos = atomicAdd(ctr, 1);
                if (pos < CAP) buf[pos] = x;
            }
        }
    }
    __syncwarp();
    return wsumi(cl);
}

// exact tie-aware select of two ranks in buf[0..cnt), broadcast result
__device__ __forceinline__ void select2c(const float* buf, int cnt, int rr0, int rr1,
                                         int lane, float* o0, float* o1) {
    float a0 = 0.f, a1 = 0.f;
    bool f0 = false, f1 = false;
    for (int base = 0; base < cnt; base += 32) {
        int idx = base + lane;
        float key = (idx < cnt) ? buf[idx] : 0.f;
        int less = 0, eq = 0;
        for (int m = 0; m < cnt; m++) {
            float c = buf[m];
            less += (c < key);
            eq   += (c == key);
        }
        if (idx < cnt) {
            if (rr0 >= less && rr0 < less + eq) { a0 = key; f0 = true; }
            if (rr1 >= less && rr1 < less + eq) { a1 = key; f1 = true; }
        }
    }
    unsigned m0 = __ballot_sync(0xffffffffu, f0);
    unsigned m1 = __ballot_sync(0xffffffffu, f1);
    int s0 = m0 ? (__ffs(m0) - 1) : 0;
    int s1 = m1 ? (__ffs(m1) - 1) : 0;
    *o0 = __shfl_sync(0xffffffffu, a0, s0);
    *o1 = __shfl_sync(0xffffffffu, a1, s1);
}

__global__ void __launch_bounds__(32 * PPB)
feat_kernel(const float* __restrict__ v, float* __restrict__ out)
{
    __shared__ float cbuf[PPB][3][CAP];
    __shared__ int   dcur[PPB][3];

    const int lane = threadIdx.x & 31;
    const int warp = threadIdx.x >> 5;
    const int p = blockIdx.x * PPB + warp;
    const int j = p % GW;
    int tmp = p / GW;
    const int i = tmp % GH;
    tmp /= GH;
    const int t = tmp % TT;
    const int b = tmp / TT;

    const int sub = lane & 7, rg = lane >> 3;
    const uint32_t base0 = (uint32_t)(b * CC * TT + t) * 50176u
                         + (uint32_t)(i * GS) * 224u + (uint32_t)(j * GS)
                         + (uint32_t)(sub * 4);

    // fixed bracketing anchors (N(0,1) data): [lo,hi) per window
    const float ALO[3] = {-0.8245f, -0.15f, 0.5245f};
    const float AHI[3] = {-0.5245f,  0.15f, 0.8245f};
    const int RMIN[3] = {767, 1535, 2303};
    const int RMAX[3] = {768, 1535, 2304};

    if (lane < 3) dcur[warp][lane] = 0;

    // ---- pass 1: moments + min/max + exact counts at 6 anchors ----
    float S1 = 0.f, S2 = 0.f, S3 = 0.f, S4 = 0.f;
    float mn = INFINITY, mx = -INFINITY;
    int n0 = 0, n1 = 0, n2 = 0, n3 = 0, n4 = 0, n5 = 0;
    #pragma unroll 4
    for (int k = 0; k < 24; k++) {
        int r = k * 4 + rg;
        uint32_t idx = base0 + (uint32_t)(r >> 5) * CHS + (uint32_t)(r & 31) * 224u;
        float4 x4 = *reinterpret_cast<const float4*>(v + idx);
        float xs[4] = {x4.x, x4.y, x4.z, x4.w};
        #pragma unroll
        for (int e = 0; e < 4; e++) {
            float x = xs[e];
            float x2 = x * x;
            S1 += x; S2 += x2;
            S3 = fmaf(x2, x, S3);
            S4 = fmaf(x2, x2, S4);
            mn = fminf(mn, x);
            mx = fmaxf(mx, x);
            n0 += (x < ALO[0]); n1 += (x < AHI[0]);
            n2 += (x < ALO[1]); n3 += (x < AHI[1]);
            n4 += (x < ALO[2]); n5 += (x < AHI[2]);
        }
    }
    S1 = wsumf(S1); S2 = wsumf(S2); S3 = wsumf(S3); S4 = wsumf(S4);
    mn = wminf(mn); mx = wmaxf(mx);
    int pk0 = wsumi(n0 | (n1 << 16));
    int pk1 = wsumi(n2 | (n3 << 16));
    int pk2 = wsumi(n4 | (n5 << 16));
    int cla[3] = {pk0 & 0xFFFF, pk1 & 0xFFFF, pk2 & 0xFFFF};
    int cha[3] = {pk0 >> 16,    pk1 >> 16,    pk2 >> 16};

    float ql[3], qh[3];
    if (mx == mn) {
        ql[0] = qh[0] = ql[1] = qh[1] = ql[2] = qh[2] = mn;
    } else {
        // ---- interpolated tight windows (GUARD ranks of slack) ----
        bool aok[3];
        float plo[3], phi[3];
        #pragma unroll
        for (int w = 0; w < 3; w++) {
            aok[w] = (cla[w] <= RMIN[w]) && (RMAX[w] < cha[w]);
            float span = AHI[w] - ALO[w];
            float inv = 1.0f / (float)max(cha[w] - cla[w], 1);
            float gl = ALO[w] + ((float)RMIN[w] - GUARD - (float)cla[w]) * inv * span;
            float gh = ALO[w] + ((float)RMAX[w] + GUARD + 1.0f - (float)cla[w]) * inv * span;
            plo[w] = fmaxf(ALO[w], gl);
            phi[w] = fminf(AHI[w], gh);
        }
        __syncwarp();

        // ---- pass 2: count below plo + atomic gather of [plo,phi) ----
        int c0 = 0, c1 = 0, c2 = 0;
        #pragma unroll 4
        for (int k = 0; k < 24; k++) {
            int r = k * 4 + rg;
            uint32_t idx = base0 + (uint32_t)(r >> 5) * CHS + (uint32_t)(r & 31) * 224u;
            float4 x4 = *reinterpret_cast<const float4*>(v + idx);
            float xs[4] = {x4.x, x4.y, x4.z, x4.w};
            #pragma unroll
            for (int e = 0; e < 4; e++) {
                float x = xs[e];
                bool l0 = x < plo[0]; c0 += l0;
                if (!l0 && x < phi[0]) {
                    int pos = atomicAdd(&dcur[warp][0], 1);
                    if (pos < CAP) cbuf[warp][0][pos] = x;
                }
                bool l1 = x < plo[1]; c1 += l1;
                if (!l1 && x < phi[1]) {
                    int pos = atomicAdd(&dcur[warp][1], 1);
                    if (pos < CAP) cbuf[warp][1][pos] = x;
                }
                bool l2 = x < plo[2]; c2 += l2;
                if (!l2 && x < phi[2]) {
                    int pos = atomicAdd(&dcur[warp][2], 1);
                    if (pos < CAP) cbuf[warp][2][pos] = x;
                }
            }
        }
        int q01 = wsumi(c0 | (c1 << 16));
        c2 = wsumi(c2);
        int cl[3] = {q01 & 0xFFFF, q01 >> 16, c2};
        __syncwarp();

        #pragma unroll
        for (int w = 0; w < 3; w++) {
            int g = dcur[warp][w];
            if (g <= CAP && cl[w] <= RMIN[w] && RMAX[w] < cl[w] + g) {
                select2c(cbuf[warp][w], g, RMIN[w] - cl[w], RMAX[w] - cl[w],
                         lane, &ql[w], &qh[w]);
            } else if (aok[w]) {
                // middle fallback: one extra pass, full anchor window
                int cl2 = gather_window(v, base0, rg, sub, lane,
                                        ALO[w], AHI[w], cbuf[warp][w], &dcur[warp][w]);
                int g2 = dcur[warp][w];
                if (g2 <= CAP && cl2 <= RMIN[w] && RMAX[w] < cl2 + g2) {
                    select2c(cbuf[warp][w], g2, RMIN[w] - cl2, RMAX[w] - cl2,
                             lane, &ql[w], &qh[w]);
                } else {
                    ql[w] = slow_rank(v, base0, rg, sub, RMIN[w]);
                    qh[w] = (RMAX[w] == RMIN[w]) ? ql[w]
                            : slow_rank(v, base0, rg, sub, RMAX[w]);
                }
            } else {
                ql[w] = slow_rank(v, base0, rg, sub, RMIN[w]);
                qh[w] = (RMAX[w] == RMIN[w]) ? ql[w]
                        : slow_rank(v, base0, rg, sub, RMAX[w]);
            }
        }
    }

    if (lane == 0) {
        const double n = (double)NPP;
        double s1 = S1, s2 = S2, s3 = S3, s4 = S4;
        double mean = s1 / n;
        double c2m = s2 - n * mean * mean;
        double c3m = s3 - 3.0 * mean * s2 + 2.0 * n * mean * mean * mean;
        double m2s = mean * mean;
        double c4m = s4 - 4.0 * mean * s3 + 6.0 * m2s * s2 - 3.0 * n * m2s * m2s;
        double sd = sqrt(c2m / (n - 1.0));
        double sde = sd + 1e-8;
        double energy = s2 / n;
        double rms = sqrt(energy + 1e-8);
        double i3 = 1.0 / (sde * sde * sde);
        double skew = (c3m / n) * i3;
        double kurt = (c4m / n) * i3 / sde - 3.0;
        float q25 = ql[0] * 0.25f + qh[0] * 0.75f;
        float q75 = ql[2] * 0.75f + qh[2] * 0.25f;

        float* o = out + (size_t)p * 10;
        o[0] = (float)mean; o[1] = (float)sd; o[2] = mn; o[3] = mx;
        o[4] = (float)energy; o[5] = (float)rms; o[6] = (float)skew;
        o[7] = (float)kurt; o[8] = ql[1]; o[9] = q75 - q25;
    }
}

__device__ __forceinline__ int tau_t(int t) {
    int c = 0;
    if (t + 1 < TT) c++;
    if (t - 1 >= 0) c++;
    if (t + 2 < TT) c++;
    if (t - 2 >= 0) c++;
    return c;
}

__global__ void edge_kernel(float* __restrict__ out)
{
    int node = blockIdx.x * blockDim.x + threadIdx.x;
    if (node >= NODES) return;
    int t = node / NPF;
    int rem = node % NPF;
    int i = rem / GW;
    int j = rem % GW;

    int mt = t < 30 ? t : 30;
    int cum_tau = (t > 0 ? 2 : 0) + (t > 1 ? 3 : 0)
                + 4 * (mt > 2 ? (mt - 2) : 0) + (t > 30 ? 3 : 0);
    int taut = tau_t(t);
    int rowpref = (i == 0) ? 0 : (31 + 50 * (i - 1));
    int ci = (i == 0 || i == GH - 1) ? 2 : 3;
    int cumcj = (j > 0 ? 2 : 0) + 3 * (j > 1 ? (j - 1) : 0);
    int sp = rowpref + ci * cumcj - j;
    int off = 312 * t + 49 * cum_tau + sp + rem * taut;

    const int di[8] = {-1,-1,-1, 0, 0, 1, 1, 1};
    const int dj[8] = {-1, 0, 1,-1, 1,-1, 0, 1};
    int e = off;
    float fnode = (float)node;
    #pragma unroll
    for (int q = 0; q < 8; q++) {
        int ni = i + di[q], nj = j + dj[q];
        if (ni >= 0 && ni < GH && nj >= 0 && nj < GW) {
            out[e]         = fnode;
            out[NEDGE + e] = (float)(t * NPF + ni * GW + nj);
            e++;
        }
    }
    const int dts[4] = {1, -1, 2, -2};
    #pragma unroll
    for (int q = 0; q < 4; q++) {
        int tt2 = t + dts[q];
        if (tt2 >= 0 && tt2 < TT) {
            out[e]         = fnode;
            out[NEDGE + e] = (float)(tt2 * NPF + i * GW + j);
            e++;
        }
    }
}

extern "C" void kernel_launch(void* const* d_in, const int* in_sizes, int n_in,
                              void* d_out, int out_size)
{
    const float* video = (const float*)d_in[0];
    float* out = (float*)d_out;

    if (out_size >= XFLOATS + 2 * NEDGE) {
        edge_kernel<<<(NODES + 255) / 256, 256>>>(out + XFLOATS);
    }
    feat_kernel<<<NPATCH / PPB, 32 * PPB>>>(video, out);
}

// round 11
// speedup vs baseline: 3.1772x; 1.0074x over previous
#include <cuda_runtime.h>
#include <math.h>
#include <stdint.h>

#define BB 16
#define CC 3
#define TT 32
#define HH 224
#define WW 224
#define GS 32
#define GH 7
#define GW 7
#define NPF 49
#define NODES 1568
#define NPATCH 25088
#define NPP 3072
#define NEDGE 15962
#define XFLOATS 250880
#define CAP 288
#define SUBCAP 96
#define PPB 4
#define GUARD 26.0f
#define CHS 1605632u     // channel stride in elements (32*224*224)

// fixed tight windows: quantile value +/- 3.5 sigma_q for N(0,1), n=3072
#define W0LO (-0.7606f)
#define W0HI (-0.5884f)
#define W1LO (-0.0791f)
#define W1HI ( 0.0791f)
#define W2LO ( 0.5884f)
#define W2HI ( 0.7606f)

__device__ __forceinline__ float wsumf(float x) {
    #pragma unroll
    for (int o = 16; o; o >>= 1) x += __shfl_xor_sync(0xffffffffu, x, o);
    return x;
}
__device__ __forceinline__ int wsumi(int x) {
    #pragma unroll
    for (int o = 16; o; o >>= 1) x += __shfl_xor_sync(0xffffffffu, x, o);
    return x;
}
__device__ __forceinline__ float wminf(float x) {
    #pragma unroll
    for (int o = 16; o; o >>= 1) x = fminf(x, __shfl_xor_sync(0xffffffffu, x, o));
    return x;
}
__device__ __forceinline__ float wmaxf(float x) {
    #pragma unroll
    for (int o = 16; o; o >>= 1) x = fmaxf(x, __shfl_xor_sync(0xffffffffu, x, o));
    return x;
}

__device__ __forceinline__ uint32_t xform(float f) {
    uint32_t u = __float_as_uint(f);
    return (u & 0x80000000u) ? ~u : (u | 0x80000000u);
}
__device__ __forceinline__ float unxform(uint32_t u) {
    u = (u & 0x80000000u) ? (u ^ 0x80000000u) : ~u;
    return __uint_as_float(u);
}

// exact count of xform(x) <= code over the patch (gmem; cold path)
__device__ __noinline__ int count_le_code(const float* __restrict__ v, uint32_t base0,
                                          int rg, uint32_t code) {
    int c = 0;
    for (int k = 0; k < 24; k++) {
        int r = k * 4 + rg;
        uint32_t idx = base0 + (uint32_t)(r >> 5) * CHS + (uint32_t)(r & 31) * 224u;
        float4 x4 = *reinterpret_cast<const float4*>(v + idx);
        c += (xform(x4.x) <= code) + (xform(x4.y) <= code)
           + (xform(x4.z) <= code) + (xform(x4.w) <= code);
    }
    return wsumi(c);
}

// guaranteed-exact rank select via bisection over float code space (cold path)
__device__ __noinline__ float slow_rank(const float* __restrict__ v, uint32_t base0,
                                        int rg, int r) {
    uint32_t lo = 0u, hi = 0xFFFFFFFFu;
    while (lo < hi) {
        uint32_t mid = lo + ((hi - lo) >> 1);
        int c = count_le_code(v, base0, rg, mid);
        if (c >= r + 1) hi = mid; else lo = mid + 1;
    }
    return unxform(lo);
}

// exact tie-aware select of two ranks in buf[0..cnt), broadcast result
__device__ __forceinline__ void select2c(const float* buf, int cnt, int rr0, int rr1,
                                         int lane, float* o0, float* o1) {
    float a0 = 0.f, a1 = 0.f;
    bool f0 = false, f1 = false;
    for (int base = 0; base < cnt; base += 32) {
        int idx = base + lane;
        float key = (idx < cnt) ? buf[idx] : 0.f;
        int less = 0, eq = 0;
        for (int m = 0; m < cnt; m++) {
            float c = buf[m];
            less += (c < key);
            eq   += (c == key);
        }
        if (idx < cnt) {
            if (rr0 >= less && rr0 < less + eq) { a0 = key; f0 = true; }
            if (rr1 >= less && rr1 < less + eq) { a1 = key; f1 = true; }
        }
    }
    unsigned m0 = __ballot_sync(0xffffffffu, f0);
    unsigned m1 = __ballot_sync(0xffffffffu, f1);
    int s0 = m0 ? (__ffs(m0) - 1) : 0;
    int s1 = m1 ? (__ffs(m1) - 1) : 0;
    *o0 = __shfl_sync(0xffffffffu, a0, s0);
    *o1 = __shfl_sync(0xffffffffu, a1, s1);
}

__global__ void __launch_bounds__(32 * PPB)
feat_kernel(const float* __restrict__ v, float* __restrict__ out)
{
    __shared__ float cbuf[PPB][3][CAP];
    __shared__ float sbuf[PPB][SUBCAP];
    __shared__ int   dcur[PPB][3];

    const int lane = threadIdx.x & 31;
    const int warp = threadIdx.x >> 5;
    const int p = blockIdx.x * PPB + warp;
    const int j = p % GW;
    int tmp = p / GW;
    const int i = tmp % GH;
    tmp /= GH;
    const int t = tmp % TT;
    const int b = tmp / TT;

    const int sub = lane & 7, rg = lane >> 3;
    const uint32_t base0 = (uint32_t)(b * CC * TT + t) * 50176u
                         + (uint32_t)(i * GS) * 224u + (uint32_t)(j * GS)
                         + (uint32_t)(sub * 4);

    const float WLO[3] = {W0LO, W1LO, W2LO};
    const float WHI[3] = {W0HI, W1HI, W2HI};
    const int RMIN[3] = {767, 1535, 2303};
    const int RMAX[3] = {768, 1535, 2304};

    if (lane < 3) dcur[warp][lane] = 0;
    __syncwarp();

    // ---- single fused pass: moments + min/max + counts below WLO + window gather ----
    float S1 = 0.f, S2 = 0.f, S3 = 0.f, S4 = 0.f;
    float mn = INFINITY, mx = -INFINITY;
    int c0 = 0, c1 = 0, c2 = 0;
    #pragma unroll 4
    for (int k = 0; k < 24; k++) {
        int r = k * 4 + rg;
        uint32_t idx = base0 + (uint32_t)(r >> 5) * CHS + (uint32_t)(r & 31) * 224u;
        float4 x4 = *reinterpret_cast<const float4*>(v + idx);
        float xs[4] = {x4.x, x4.y, x4.z, x4.w};
        #pragma unroll
        for (int e = 0; e < 4; e++) {
            float x = xs[e];
            float x2 = x * x;
            S1 += x; S2 += x2;
            S3 = fmaf(x2, x, S3);
            S4 = fmaf(x2, x2, S4);
            mn = fminf(mn, x);
            mx = fmaxf(mx, x);
            bool l0 = x < W0LO; c0 += l0;
            if (!l0 && x < W0HI) {
                int pos = atomicAdd(&dcur[warp][0], 1);
                if (pos < CAP) cbuf[warp][0][pos] = x;
            }
            bool l1 = x < W1LO; c1 += l1;
            if (!l1 && x < W1HI) {
                int pos = atomicAdd(&dcur[warp][1], 1);
                if (pos < CAP) cbuf[warp][1][pos] = x;
            }
            bool l2 = x < W2LO; c2 += l2;
            if (!l2 && x < W2HI) {
                int pos = atomicAdd(&dcur[warp][2], 1);
                if (pos < CAP) cbuf[warp][2][pos] = x;
            }
        }
    }
    S1 = wsumf(S1); S2 = wsumf(S2); S3 = wsumf(S3); S4 = wsumf(S4);
    mn = wminf(mn); mx = wmaxf(mx);
    int pk = wsumi(c0 | (c1 << 16));
    c2 = wsumi(c2);
    int cla[3] = {pk & 0xFFFF, pk >> 16, c2};
    __syncwarp();

    // ---- per-window smem refinement + exact select ----
    float ql[3], qh[3];
    const unsigned ltm = (1u << lane) - 1u;
    #pragma unroll
    for (int w = 0; w < 3; w++) {
        const int g = dcur[warp][w];
        const int rmin = RMIN[w], rmax = RMAX[w];
        const int cl = cla[w];
        if (g <= CAP && cl <= rmin && rmax < cl + g) {
            // interpolate tight sub-window within buffer
            float span = WHI[w] - WLO[w];
            float inv = span / (float)g;
            float plo2 = WLO[w] + ((float)rmin - GUARD - (float)cl) * inv;
            float phi2 = WLO[w] + ((float)rmax + GUARD + 1.0f - (float)cl) * inv;
            plo2 = fmaxf(plo2, WLO[w]);
            phi2 = fminf(phi2, WHI[w]);

            // ballot sub-gather over the smem buffer (~6-9 iterations)
            const float* bw = cbuf[warp][w];
            int elo = 0, sc = 0;
            for (int bidx = 0; bidx < g; bidx += 32) {
                int idx = bidx + lane;
                bool val = idx < g;
                float x = val ? bw[idx] : 0.f;
                elo += val && (x < plo2);
                bool inb = val && (x >= plo2) && (x < phi2);
                unsigned mk = __ballot_sync(0xffffffffu, inb);
                if (inb) {
                    int pos = sc + __popc(mk & ltm);
                    if (pos < SUBCAP) sbuf[warp][pos] = x;
                }
                sc += __popc(mk);
            }
            elo = wsumi(elo);
            __syncwarp();
            int basr = cl + elo;
            if (sc <= SUBCAP && basr <= rmin && rmax < basr + sc) {
                select2c(sbuf[warp], sc, rmin - basr, rmax - basr, lane, &ql[w], &qh[w]);
            } else {
                // exact select over the full window buffer (rare)
                select2c(bw, g, rmin - cl, rmax - cl, lane, &ql[w], &qh[w]);
            }
            __syncwarp();
        } else {
            // window missed the rank (≈1e-4 of patches) or overflow: exact cold path
            ql[w] = slow_rank(v, base0, rg, rmin);
            qh[w] = (rmax == rmin) ? ql[w] : slow_rank(v, base0, rg, rmax);
        }
    }

    if (lane == 0) {
        const double n = (double)NPP;
        double s1 = S1, s2 = S2, s3 = S3, s4 = S4;
        double mean = s1 / n;
        double c2m = s2 - n * mean * mean;
        double c3m = s3 - 3.0 * mean * s2 + 2.0 * n * mean * mean * mean;
        double m2s = mean * mean;
        double c4m = s4 - 4.0 * mean * s3 + 6.0 * m2s * s2 - 3.0 * n * m2s * m2s;
        double sd = sqrt(c2m / (n - 1.0));
        double sde = sd + 1e-8;
        double energy = s2 / n;
        double rms = sqrt(energy + 1e-8);
        double i3 = 1.0 / (sde * sde * sde);
        double skew = (c3m / n) * i3;
        double kurt = (c4m / n) * i3 / sde - 3.0;
        float q25 = ql[0] * 0.25f + qh[0] * 0.75f;
        float q75 = ql[2] * 0.75f + qh[2] * 0.25f;

        float* o = out + (size_t)p * 10;
        o[0] = (float)mean; o[1] = (float)sd; o[2] = mn; o[3] = mx;
        o[4] = (float)energy; o[5] = (float)rms; o[6] = (float)skew;
        o[7] = (float)kurt; o[8] = ql[1]; o[9] = q75 - q25;
    }
}

__device__ __forceinline__ int tau_t(int t) {
    int c = 0;
    if (t + 1 < TT) c++;
    if (t - 1 >= 0) c++;
    if (t + 2 < TT) c++;
    if (t - 2 >= 0) c++;
    return c;
}

__global__ void edge_kernel(float* __restrict__ out)
{
    int node = blockIdx.x * blockDim.x + threadIdx.x;
    if (node >= NODES) return;
    int t = node / NPF;
    int rem = node % NPF;
    int i = rem / GW;
    int j = rem % GW;

    int mt = t < 30 ? t : 30;
    int cum_tau = (t > 0 ? 2 : 0) + (t > 1 ? 3 : 0)
                + 4 * (mt > 2 ? (mt - 2) : 0) + (t > 30 ? 3 : 0);
    int taut = tau_t(t);
    int rowpref = (i == 0) ? 0 : (31 + 50 * (i - 1));
    int ci = (i == 0 || i == GH - 1) ? 2 : 3;
    int cumcj = (j > 0 ? 2 : 0) + 3 * (j > 1 ? (j - 1) : 0);
    int sp = rowpref + ci * cumcj - j;
    int off = 312 * t + 49 * cum_tau + sp + rem * taut;

    const int di[8] = {-1,-1,-1, 0, 0, 1, 1, 1};
    const int dj[8] = {-1, 0, 1,-1, 1,-1, 0, 1};
    int e = off;
    float fnode = (float)node;
    #pragma unroll
    for (int q = 0; q < 8; q++) {
        int ni = i + di[q], nj = j + dj[q];
        if (ni >= 0 && ni < GH && nj >= 0 && nj < GW) {
            out[e]         = fnode;
            out[NEDGE + e] = (float)(t * NPF + ni * GW + nj);
            e++;
        }
    }
    const int dts[4] = {1, -1, 2, -2};
    #pragma unroll
    for (int q = 0; q < 4; q++) {
        int tt2 = t + dts[q];
        if (tt2 >= 0 && tt2 < TT) {
            out[e]         = fnode;
            out[NEDGE + e] = (float)(tt2 * NPF + i * GW + j);
            e++;
        }
    }
}

extern "C" void kernel_launch(void* const* d_in, const int* in_sizes, int n_in,
                              void* d_out, int out_size)
{
    const float* video = (const float*)d_in[0];
    float* out = (float*)d_out;

    if (out_size >= XFLOATS + 2 * NEDGE) {
        edge_kernel<<<(NODES + 255) / 256, 256>>>(out + XFLOATS);
    }
    feat_kernel<<<NPATCH / PPB, 32 * PPB>>>(video, out);
}

// round 12
// speedup vs baseline: 3.5276x; 1.1103x over previous
#include <cuda_runtime.h>
#include <math.h>
#include <stdint.h>

#define BB 16
#define CC 3
#define TT 32
#define HH 224
#define WW 224
#define GS 32
#define GH 7
#define GW 7
#define NPF 49
#define NODES 1568
#define NPATCH 25088
#define NPP 3072
#define NEDGE 15962
#define XFLOATS 250880
#define CAP 288
#define SUBCAP 64
#define PPB 4
#define GUARD 22.0f
#define CHS 1605632u     // channel stride in elements (32*224*224)

// fixed tight windows: quantile value +/- 3.5 sigma_q for N(0,1), n=3072
#define W0LO (-0.7606f)
#define W0HI (-0.5884f)
#define W1LO (-0.0791f)
#define W1HI ( 0.0791f)
#define W2LO ( 0.5884f)
#define W2HI ( 0.7606f)

__device__ __forceinline__ float wsumf(float x) {
    #pragma unroll
    for (int o = 16; o; o >>= 1) x += __shfl_xor_sync(0xffffffffu, x, o);
    return x;
}
__device__ __forceinline__ int wsumi(int x) {
    #pragma unroll
    for (int o = 16; o; o >>= 1) x += __shfl_xor_sync(0xffffffffu, x, o);
    return x;
}
__device__ __forceinline__ float wminf(float x) {
    #pragma unroll
    for (int o = 16; o; o >>= 1) x = fminf(x, __shfl_xor_sync(0xffffffffu, x, o));
    return x;
}
__device__ __forceinline__ float wmaxf(float x) {
    #pragma unroll
    for (int o = 16; o; o >>= 1) x = fmaxf(x, __shfl_xor_sync(0xffffffffu, x, o));
    return x;
}

__device__ __forceinline__ uint32_t xform(float f) {
    uint32_t u = __float_as_uint(f);
    return (u & 0x80000000u) ? ~u : (u | 0x80000000u);
}
__device__ __forceinline__ float unxform(uint32_t u) {
    u = (u & 0x80000000u) ? (u ^ 0x80000000u) : ~u;
    return __uint_as_float(u);
}

// packed f32x2 helpers
__device__ __forceinline__ uint64_t pk2(float a, float b) {
    uint64_t r; asm("mov.b64 %0,{%1,%2};" : "=l"(r) : "f"(a), "f"(b)); return r;
}
__device__ __forceinline__ void upk2(uint64_t p, float& a, float& b) {
    asm("mov.b64 {%0,%1},%2;" : "=f"(a), "=f"(b) : "l"(p));
}
__device__ __forceinline__ uint64_t add2(uint64_t a, uint64_t b) {
    uint64_t r; asm("add.rn.f32x2 %0,%1,%2;" : "=l"(r) : "l"(a), "l"(b)); return r;
}
__device__ __forceinline__ uint64_t mul2(uint64_t a, uint64_t b) {
    uint64_t r; asm("mul.rn.f32x2 %0,%1,%2;" : "=l"(r) : "l"(a), "l"(b)); return r;
}
__device__ __forceinline__ uint64_t fma2(uint64_t a, uint64_t b, uint64_t c) {
    uint64_t r; asm("fma.rn.f32x2 %0,%1,%2,%3;" : "=l"(r) : "l"(a), "l"(b), "l"(c)); return r;
}

// exact count of xform(x) <= code over the patch (gmem; cold path)
__device__ __noinline__ int count_le_code(const float* __restrict__ v, uint32_t base0,
                                          int rg, uint32_t code) {
    int c = 0;
    for (int k = 0; k < 24; k++) {
        int r = k * 4 + rg;
        uint32_t idx = base0 + (uint32_t)(r >> 5) * CHS + (uint32_t)(r & 31) * 224u;
        float4 x4 = *reinterpret_cast<const float4*>(v + idx);
        c += (xform(x4.x) <= code) + (xform(x4.y) <= code)
           + (xform(x4.z) <= code) + (xform(x4.w) <= code);
    }
    return wsumi(c);
}

// guaranteed-exact rank select via bisection over float code space (cold path)
__device__ __noinline__ float slow_rank(const float* __restrict__ v, uint32_t base0,
                                        int rg, int r) {
    uint32_t lo = 0u, hi = 0xFFFFFFFFu;
    while (lo < hi) {
        uint32_t mid = lo + ((hi - lo) >> 1);
        int c = count_le_code(v, base0, rg, mid);
        if (c >= r + 1) hi = mid; else lo = mid + 1;
    }
    return unxform(lo);
}

// exact tie-aware select of two ranks in buf[0..cnt), broadcast (cold fallback)
__device__ __noinline__ void select2c(const float* buf, int cnt, int rr0, int rr1,
                                      int lane, float* o0, float* o1) {
    float a0 = 0.f, a1 = 0.f;
    bool f0 = false, f1 = false;
    for (int base = 0; base < cnt; base += 32) {
        int idx = base + lane;
        float key = (idx < cnt) ? buf[idx] : 0.f;
        int less = 0, eq = 0;
        for (int m = 0; m < cnt; m++) {
            float c = buf[m];
            less += (c < key);
            eq   += (c == key);
        }
        if (idx < cnt) {
            if (rr0 >= less && rr0 < less + eq) { a0 = key; f0 = true; }
            if (rr1 >= less && rr1 < less + eq) { a1 = key; f1 = true; }
        }
    }
    unsigned m0 = __ballot_sync(0xffffffffu, f0);
    unsigned m1 = __ballot_sync(0xffffffffu, f1);
    int s0 = m0 ? (__ffs(m0) - 1) : 0;
    int s1 = m1 ? (__ffs(m1) - 1) : 0;
    *o0 = __shfl_sync(0xffffffffu, a0, s0);
    *o1 = __shfl_sync(0xffffffffu, a1, s1);
}

// bitonic sort of 64 values: a at index lane, b at index lane+32, ascending
__device__ __forceinline__ void bitonic64(float& a, float& b, int lane) {
    #pragma unroll
    for (int k = 2; k <= 32; k <<= 1) {
        #pragma unroll
        for (int j = k >> 1; j >= 1; j >>= 1) {
            {
                float pa = __shfl_xor_sync(0xffffffffu, a, j);
                bool up = ((lane & k) == 0);
                bool lower = ((lane & j) == 0);
                a = (lower == up) ? fminf(a, pa) : fmaxf(a, pa);
            }
            {
                float pb = __shfl_xor_sync(0xffffffffu, b, j);
                bool up = (k == 32) ? false : ((lane & k) == 0);
                bool lower = ((lane & j) == 0);
                b = (lower == up) ? fminf(b, pb) : fmaxf(b, pb);
            }
        }
    }
    // k = 64 merge (ascending): j=32 pairs (lane, lane+32) locally
    {
        float lo = fminf(a, b), hi = fmaxf(a, b);
        a = lo; b = hi;
    }
    #pragma unroll
    for (int j = 16; j >= 1; j >>= 1) {
        {
            float pa = __shfl_xor_sync(0xffffffffu, a, j);
            bool lower = ((lane & j) == 0);
            a = lower ? fminf(a, pa) : fmaxf(a, pa);
        }
        {
            float pb = __shfl_xor_sync(0xffffffffu, b, j);
            bool lower = ((lane & j) == 0);
            b = lower ? fminf(b, pb) : fmaxf(b, pb);
        }
    }
}
__device__ __forceinline__ float sorted_at(float a, float b, int r) {
    float va = __shfl_sync(0xffffffffu, a, r & 31);
    float vb = __shfl_sync(0xffffffffu, b, r & 31);
    return (r < 32) ? va : vb;
}

__global__ void __launch_bounds__(32 * PPB, 10)
feat_kernel(const float* __restrict__ v, float* __restrict__ out)
{
    __shared__ float cbuf[PPB][3][CAP];
    __shared__ float sbuf[PPB][SUBCAP];
    __shared__ int   dcur[PPB][3];

    const int lane = threadIdx.x & 31;
    const int warp = threadIdx.x >> 5;
    const int p = blockIdx.x * PPB + warp;
    const int j = p % GW;
    int tmp = p / GW;
    const int i = tmp % GH;
    tmp /= GH;
    const int t = tmp % TT;
    const int b = tmp / TT;

    const int sub = lane & 7, rg = lane >> 3;
    const uint32_t base0 = (uint32_t)(b * CC * TT + t) * 50176u
                         + (uint32_t)(i * GS) * 224u + (uint32_t)(j * GS)
                         + (uint32_t)(sub * 4);

    const float WLO[3] = {W0LO, W1LO, W2LO};
    const float WHI[3] = {W0HI, W1HI, W2HI};
    const int RMIN[3] = {767, 1535, 2303};
    const int RMAX[3] = {768, 1535, 2304};

    if (lane < 3) dcur[warp][lane] = 0;
    __syncwarp();

    // ---- single fused pass: packed moments + min/max + counts + merged gather ----
    uint64_t S1p = 0, S2p = 0, S3p = 0, S4p = 0;
    float mn = INFINITY, mx = -INFINITY;
    int c0 = 0, c1 = 0, c2 = 0;
    #pragma unroll 4
    for (int k = 0; k < 24; k++) {
        int r = k * 4 + rg;
        uint32_t idx = base0 + (uint32_t)(r >> 5) * CHS + (uint32_t)(r & 31) * 224u;
        float4 x4 = *reinterpret_cast<const float4*>(v + idx);

        uint64_t pA = pk2(x4.x, x4.y), pB = pk2(x4.z, x4.w);
        uint64_t qA = mul2(pA, pA), qB = mul2(pB, pB);
        S1p = add2(S1p, pA); S1p = add2(S1p, pB);
        S2p = add2(S2p, qA); S2p = add2(S2p, qB);
        S3p = fma2(qA, pA, S3p); S3p = fma2(qB, pB, S3p);
        S4p = fma2(qA, qA, S4p); S4p = fma2(qB, qB, S4p);

        float xs[4] = {x4.x, x4.y, x4.z, x4.w};
        #pragma unroll
        for (int e = 0; e < 4; e++) {
            float x = xs[e];
            mn = fminf(mn, x);
            mx = fmaxf(mx, x);
            bool l0 = x < W0LO; c0 += l0;
            bool l1 = x < W1LO; c1 += l1;
            bool l2 = x < W2LO; c2 += l2;
            if (!l0 && x < W2HI) {           // coarse region (windows disjoint)
                int wsel = 2;
                bool in = true;
                if (x < W0HI)      { wsel = 0; }
                else if (l1)       { in = false; }
                else if (x < W1HI) { wsel = 1; }
                else if (l2)       { in = false; }
                if (in) {
                    int pos = atomicAdd(&dcur[warp][wsel], 1);
                    if (pos < CAP) cbuf[warp][wsel][pos] = x;
                }
            }
        }
    }
    float s1a, s1b, s2a, s2b, s3a, s3b, s4a, s4b;
    upk2(S1p, s1a, s1b); upk2(S2p, s2a, s2b);
    upk2(S3p, s3a, s3b); upk2(S4p, s4a, s4b);
    float S1 = wsumf(s1a + s1b), S2 = wsumf(s2a + s2b);
    float S3 = wsumf(s3a + s3b), S4 = wsumf(s4a + s4b);
    mn = wminf(mn); mx = wmaxf(mx);
    int pk = wsumi(c0 | (c1 << 16));
    c2 = wsumi(c2);
    int cla[3] = {pk & 0xFFFF, pk >> 16, c2};
    __syncwarp();

    // ---- per-window smem refinement + sort-based exact select ----
    float ql[3], qh[3];
    const unsigned ltm = (1u << lane) - 1u;
    #pragma unroll
    for (int w = 0; w < 3; w++) {
        const int g = dcur[warp][w];
        const int rmin = RMIN[w], rmax = RMAX[w];
        const int cl = cla[w];
        if (g <= CAP && cl <= rmin && rmax < cl + g) {
            // interpolate tight sub-window within buffer
            float span = WHI[w] - WLO[w];
            float inv = span / (float)g;
            float plo2 = WLO[w] + ((float)rmin - GUARD - (float)cl) * inv;
            float phi2 = WLO[w] + ((float)rmax + GUARD + 1.0f - (float)cl) * inv;
            plo2 = fmaxf(plo2, WLO[w]);
            phi2 = fminf(phi2, WHI[w]);

            // ballot sub-gather over the smem buffer
            const float* bw = cbuf[warp][w];
            int elo = 0, sc = 0;
            for (int bidx = 0; bidx < g; bidx += 32) {
                int idx = bidx + lane;
                bool val = idx < g;
                float x = val ? bw[idx] : 0.f;
                elo += val && (x < plo2);
                bool inb = val && (x >= plo2) && (x < phi2);
                unsigned mk = __ballot_sync(0xffffffffu, inb);
                if (inb) {
                    int pos = sc + __popc(mk & ltm);
                    if (pos < SUBCAP) sbuf[warp][pos] = x;
                }
                sc += __popc(mk);
            }
            elo = wsumi(elo);
            __syncwarp();
            int basr = cl + elo;
            if (sc <= SUBCAP && basr <= rmin && rmax < basr + sc) {
                float aa = (lane < sc) ? sbuf[warp][lane] : INFINITY;
                float bb = (lane + 32 < sc) ? sbuf[warp][lane + 32] : INFINITY;
                bitonic64(aa, bb, lane);
                ql[w] = sorted_at(aa, bb, rmin - basr);
                qh[w] = sorted_at(aa, bb, rmax - basr);
            } else {
                select2c(bw, g, rmin - cl, rmax - cl, lane, &ql[w], &qh[w]);
            }
            __syncwarp();
        } else {
            ql[w] = slow_rank(v, base0, rg, rmin);
            qh[w] = (rmax == rmin) ? ql[w] : slow_rank(v, base0, rg, rmax);
        }
    }

    if (lane == 0) {
        const double n = (double)NPP;
        double s1 = S1, s2 = S2, s3 = S3, s4 = S4;
        double mean = s1 / n;
        double c2m = s2 - n * mean * mean;
        double c3m = s3 - 3.0 * mean * s2 + 2.0 * n * mean * mean * mean;
        double m2s = mean * mean;
        double c4m = s4 - 4.0 * mean * s3 + 6.0 * m2s * s2 - 3.0 * n * m2s * m2s;
        double sd = sqrt(c2m / (n - 1.0));
        double sde = sd + 1e-8;
        double energy = s2 / n;
        double rms = sqrt(energy + 1e-8);
        double i3 = 1.0 / (sde * sde * sde);
        double skew = (c3m / n) * i3;
        double kurt = (c4m / n) * i3 / sde - 3.0;
        float q25 = ql[0] * 0.25f + qh[0] * 0.75f;
        float q75 = ql[2] * 0.75f + qh[2] * 0.25f;

        float* o = out + (size_t)p * 10;
        o[0] = (float)mean; o[1] = (float)sd; o[2] = mn; o[3] = mx;
        o[4] = (float)energy; o[5] = (float)rms; o[6] = (float)skew;
        o[7] = (float)kurt; o[8] = ql[1]; o[9] = q75 - q25;
    }
}

__device__ __forceinline__ int tau_t(int t) {
    int c = 0;
    if (t + 1 < TT) c++;
    if (t - 1 >= 0) c++;
    if (t + 2 < TT) c++;
    if (t - 2 >= 0) c++;
    return c;
}

__global__ void edge_kernel(float* __restrict__ out)
{
    int node = blockIdx.x * blockDim.x + threadIdx.x;
    if (node >= NODES) return;
    int t = node / NPF;
    int rem = node % NPF;
    int i = rem / GW;
    int j = rem % GW;

    int mt = t < 30 ? t : 30;
    int cum_tau = (t > 0 ? 2 : 0) + (t > 1 ? 3 : 0)
                + 4 * (mt > 2 ? (mt - 2) : 0) + (t > 30 ? 3 : 0);
    int taut = tau_t(t);
    int rowpref = (i == 0) ? 0 : (31 + 50 * (i - 1));
    int ci = (i == 0 || i == GH - 1) ? 2 : 3;
    int cumcj = (j > 0 ? 2 : 0) + 3 * (j > 1 ? (j - 1) : 0);
    int sp = rowpref + ci * cumcj - j;
    int off = 312 * t + 49 * cum_tau + sp + rem * taut;

    const int di[8] = {-1,-1,-1, 0, 0, 1, 1, 1};
    const int dj[8] = {-1, 0, 1,-1, 1,-1, 0, 1};
    int e = off;
    float fnode = (float)node;
    #pragma unroll
    for (int q = 0; q < 8; q++) {
        int ni = i + di[q], nj = j + dj[q];
        if (ni >= 0 && ni < GH && nj >= 0 && nj < GW) {
            out[e]         = fnode;
            out[NEDGE + e] = (float)(t * NPF + ni * GW + nj);
            e++;
        }
    }
    const int dts[4] = {1, -1, 2, -2};
    #pragma unroll
    for (int q = 0; q < 4; q++) {
        int tt2 = t + dts[q];
        if (tt2 >= 0 && tt2 < TT) {
            out[e]         = fnode;
            out[NEDGE + e] = (float)(tt2 * NPF + i * GW + j);
            e++;
        }
    }
}

extern "C" void kernel_launch(void* const* d_in, const int* in_sizes, int n_in,
                              void* d_out, int out_size)
{
    const float* video = (const float*)d_in[0];
    float* out = (float*)d_out;

    if (out_size >= XFLOATS + 2 * NEDGE) {
        edge_kernel<<<(NODES + 255) / 256, 256>>>(out + XFLOATS);
    }
    feat_kernel<<<NPATCH / PPB, 32 * PPB>>>(video, out);
}

// round 13
// speedup vs baseline: 3.7858x; 1.0732x over previous
#include <cuda_runtime.h>
#include <math.h>
#include <stdint.h>

#define BB 16
#define CC 3
#define TT 32
#define HH 224
#define WW 224
#define GS 32
#define GH 7
#define GW 7
#define NPF 49
#define NODES 1568
#define NPATCH 25088
#define NPP 3072
#define NEDGE 15962
#define XFLOATS 250880
#define CAP 288
#define SUBCAP 64
#define PPB 4
#define GUARD 22.0f
#define CHS 1605632u     // channel stride in elements (32*224*224)

// fixed tight windows: quantile value +/- 3.5 sigma_q for N(0,1), n=3072
#define W0LO (-0.7606f)
#define W0HI (-0.5884f)
#define W1LO (-0.0791f)
#define W1HI ( 0.0791f)
#define W2LO ( 0.5884f)
#define W2HI ( 0.7606f)

__device__ __forceinline__ float wsumf(float x) {
    #pragma unroll
    for (int o = 16; o; o >>= 1) x += __shfl_xor_sync(0xffffffffu, x, o);
    return x;
}
__device__ __forceinline__ int wsumi(int x) {
    #pragma unroll
    for (int o = 16; o; o >>= 1) x += __shfl_xor_sync(0xffffffffu, x, o);
    return x;
}
__device__ __forceinline__ float wminf(float x) {
    #pragma unroll
    for (int o = 16; o; o >>= 1) x = fminf(x, __shfl_xor_sync(0xffffffffu, x, o));
    return x;
}
__device__ __forceinline__ float wmaxf(float x) {
    #pragma unroll
    for (int o = 16; o; o >>= 1) x = fmaxf(x, __shfl_xor_sync(0xffffffffu, x, o));
    return x;
}

__device__ __forceinline__ uint32_t xform(float f) {
    uint32_t u = __float_as_uint(f);
    return (u & 0x80000000u) ? ~u : (u | 0x80000000u);
}
__device__ __forceinline__ float unxform(uint32_t u) {
    u = (u & 0x80000000u) ? (u ^ 0x80000000u) : ~u;
    return __uint_as_float(u);
}

// packed f32x2 helpers
__device__ __forceinline__ uint64_t pk2(float a, float b) {
    uint64_t r; asm("mov.b64 %0,{%1,%2};" : "=l"(r) : "f"(a), "f"(b)); return r;
}
__device__ __forceinline__ void upk2(uint64_t p, float& a, float& b) {
    asm("mov.b64 {%0,%1},%2;" : "=f"(a), "=f"(b) : "l"(p));
}
__device__ __forceinline__ uint64_t add2(uint64_t a, uint64_t b) {
    uint64_t r; asm("add.rn.f32x2 %0,%1,%2;" : "=l"(r) : "l"(a), "l"(b)); return r;
}
__device__ __forceinline__ uint64_t mul2(uint64_t a, uint64_t b) {
    uint64_t r; asm("mul.rn.f32x2 %0,%1,%2;" : "=l"(r) : "l"(a), "l"(b)); return r;
}
__device__ __forceinline__ uint64_t fma2(uint64_t a, uint64_t b, uint64_t c) {
    uint64_t r; asm("fma.rn.f32x2 %0,%1,%2,%3;" : "=l"(r) : "l"(a), "l"(b), "l"(c)); return r;
}

// exact count of xform(x) <= code over the patch (gmem; cold path)
__device__ __noinline__ int count_le_code(const float* __restrict__ v, uint32_t base0,
                                          int rg, uint32_t code) {
    int c = 0;
    for (int k = 0; k < 24; k++) {
        int r = k * 4 + rg;
        uint32_t idx = base0 + (uint32_t)(r >> 5) * CHS + (uint32_t)(r & 31) * 224u;
        float4 x4 = *reinterpret_cast<const float4*>(v + idx);
        c += (xform(x4.x) <= code) + (xform(x4.y) <= code)
           + (xform(x4.z) <= code) + (xform(x4.w) <= code);
    }
    return wsumi(c);
}

// guaranteed-exact rank select via bisection over float code space (cold path)
__device__ __noinline__ float slow_rank(const float* __restrict__ v, uint32_t base0,
                                        int rg, int r) {
    uint32_t lo = 0u, hi = 0xFFFFFFFFu;
    while (lo < hi) {
        uint32_t mid = lo + ((hi - lo) >> 1);
        int c = count_le_code(v, base0, rg, mid);
        if (c >= r + 1) hi = mid; else lo = mid + 1;
    }
    return unxform(lo);
}

// exact tie-aware select of two ranks in buf[0..cnt), broadcast (cold fallback)
__device__ __noinline__ void select2c(const float* buf, int cnt, int rr0, int rr1,
                                      int lane, float* o0, float* o1) {
    float a0 = 0.f, a1 = 0.f;
    bool f0 = false, f1 = false;
    for (int base = 0; base < cnt; base += 32) {
        int idx = base + lane;
        float key = (idx < cnt) ? buf[idx] : 0.f;
        int less = 0, eq = 0;
        for (int m = 0; m < cnt; m++) {
            float c = buf[m];
            less += (c < key);
            eq   += (c == key);
        }
        if (idx < cnt) {
            if (rr0 >= less && rr0 < less + eq) { a0 = key; f0 = true; }
            if (rr1 >= less && rr1 < less + eq) { a1 = key; f1 = true; }
        }
    }
    unsigned m0 = __ballot_sync(0xffffffffu, f0);
    unsigned m1 = __ballot_sync(0xffffffffu, f1);
    int s0 = m0 ? (__ffs(m0) - 1) : 0;
    int s1 = m1 ? (__ffs(m1) - 1) : 0;
    *o0 = __shfl_sync(0xffffffffu, a0, s0);
    *o1 = __shfl_sync(0xffffffffu, a1, s1);
}

// bitonic sort of 64 values: a at index lane, b at index lane+32, ascending
__device__ __forceinline__ void bitonic64(float& a, float& b, int lane) {
    #pragma unroll
    for (int k = 2; k <= 32; k <<= 1) {
        #pragma unroll
        for (int j = k >> 1; j >= 1; j >>= 1) {
            {
                float pa = __shfl_xor_sync(0xffffffffu, a, j);
                bool up = ((lane & k) == 0);
                bool lower = ((lane & j) == 0);
                a = (lower == up) ? fminf(a, pa) : fmaxf(a, pa);
            }
            {
                float pb = __shfl_xor_sync(0xffffffffu, b, j);
                bool up = (k == 32) ? false : ((lane & k) == 0);
                bool lower = ((lane & j) == 0);
                b = (lower == up) ? fminf(b, pb) : fmaxf(b, pb);
            }
        }
    }
    {
        float lo = fminf(a, b), hi = fmaxf(a, b);
        a = lo; b = hi;
    }
    #pragma unroll
    for (int j = 16; j >= 1; j >>= 1) {
        {
            float pa = __shfl_xor_sync(0xffffffffu, a, j);
            bool lower = ((lane & j) == 0);
            a = lower ? fminf(a, pa) : fmaxf(a, pa);
        }
        {
            float pb = __shfl_xor_sync(0xffffffffu, b, j);
            bool lower = ((lane & j) == 0);
            b = lower ? fminf(b, pb) : fmaxf(b, pb);
        }
    }
}
__device__ __forceinline__ float sorted_at(float a, float b, int r) {
    float va = __shfl_sync(0xffffffffu, a, r & 31);
    float vb = __shfl_sync(0xffffffffu, b, r & 31);
    return (r < 32) ? va : vb;
}

__global__ void __launch_bounds__(32 * PPB, 12)
feat_kernel(const float* __restrict__ v, float* __restrict__ out)
{
    __shared__ float cbuf[PPB][3][CAP];
    __shared__ float sbuf[PPB][SUBCAP];
    __shared__ int   dcur[PPB][3];

    const int lane = threadIdx.x & 31;
    const int warp = threadIdx.x >> 5;
    const int p = blockIdx.x * PPB + warp;
    const int j = p % GW;
    int tmp = p / GW;
    const int i = tmp % GH;
    tmp /= GH;
    const int t = tmp % TT;
    const int b = tmp / TT;

    const int sub = lane & 7, rg = lane >> 3;
    const uint32_t base0 = (uint32_t)(b * CC * TT + t) * 50176u
                         + (uint32_t)(i * GS) * 224u + (uint32_t)(j * GS)
                         + (uint32_t)(sub * 4);

    const float WLO[3] = {W0LO, W1LO, W2LO};
    const float WHI[3] = {W0HI, W1HI, W2HI};
    const int RMIN[3] = {767, 1535, 2303};
    const int RMAX[3] = {768, 1535, 2304};

    if (lane < 3) dcur[warp][lane] = 0;
    __syncwarp();

    // ---- single fused pass: packed moments + min/max + counts + precise gather ----
    uint64_t S1p = 0, S2p = 0, S3p = 0, S4p = 0;
    float mn = INFINITY, mx = -INFINITY;
    int c0 = 0, c1 = 0, c2 = 0;
    #pragma unroll 4
    for (int k = 0; k < 24; k++) {
        int r = k * 4 + rg;
        uint32_t idx = base0 + (uint32_t)(r >> 5) * CHS + (uint32_t)(r & 31) * 224u;
        float4 x4 = *reinterpret_cast<const float4*>(v + idx);

        uint64_t pA = pk2(x4.x, x4.y), pB = pk2(x4.z, x4.w);
        uint64_t qA = mul2(pA, pA), qB = mul2(pB, pB);
        S1p = add2(S1p, pA); S1p = add2(S1p, pB);
        S2p = add2(S2p, qA); S2p = add2(S2p, qB);
        S3p = fma2(qA, pA, S3p); S3p = fma2(qB, pB, S3p);
        S4p = fma2(qA, qA, S4p); S4p = fma2(qB, qB, S4p);

        float xs[4] = {x4.x, x4.y, x4.z, x4.w};
        #pragma unroll
        for (int e = 0; e < 4; e++) {
            float x = xs[e];
            mn = fminf(mn, x);
            mx = fmaxf(mx, x);
            bool l0 = x < W0LO; c0 += l0;
            bool l1 = x < W1LO; c1 += l1;
            bool l2 = x < W2LO; c2 += l2;
            bool in0 = (!l0) && (x < W0HI);
            bool in1 = (!l1) && (x < W1HI);
            bool in2 = (!l2) && (x < W2HI);
            if (in0 | in1 | in2) {                 // ~17% entry rate
                int wsel = in1 ? 1 : (in0 ? 0 : 2);
                int pos = atomicAdd(&dcur[warp][wsel], 1);
                if (pos < CAP) cbuf[warp][wsel][pos] = x;
            }
        }
    }
    float s1a, s1b, s2a, s2b, s3a, s3b, s4a, s4b;
    upk2(S1p, s1a, s1b); upk2(S2p, s2a, s2b);
    upk2(S3p, s3a, s3b); upk2(S4p, s4a, s4b);
    float S1 = wsumf(s1a + s1b), S2 = wsumf(s2a + s2b);
    float S3 = wsumf(s3a + s3b), S4 = wsumf(s4a + s4b);
    mn = wminf(mn); mx = wmaxf(mx);
    int pk = wsumi(c0 | (c1 << 16));
    c2 = wsumi(c2);
    int cla[3] = {pk & 0xFFFF, pk >> 16, c2};
    __syncwarp();

    // ---- per-window smem refinement + sort-based exact select ----
    float ql[3], qh[3];
    const unsigned ltm = (1u << lane) - 1u;
    #pragma unroll
    for (int w = 0; w < 3; w++) {
        const int g = dcur[warp][w];
        const int rmin = RMIN[w], rmax = RMAX[w];
        const int cl = cla[w];
        if (g <= CAP && cl <= rmin && rmax < cl + g) {
            float span = WHI[w] - WLO[w];
            float inv = span / (float)g;
            float plo2 = WLO[w] + ((float)rmin - GUARD - (float)cl) * inv;
            float phi2 = WLO[w] + ((float)rmax + GUARD + 1.0f - (float)cl) * inv;
            plo2 = fmaxf(plo2, WLO[w]);
            phi2 = fminf(phi2, WHI[w]);

            const float* bw = cbuf[warp][w];
            int elo = 0, sc = 0;
            #pragma unroll 3
            for (int bidx = 0; bidx < g; bidx += 32) {
                int idx = bidx + lane;
                bool val = idx < g;
                float x = val ? bw[idx] : 0.f;
                elo += val && (x < plo2);
                bool inb = val && (x >= plo2) && (x < phi2);
                unsigned mk = __ballot_sync(0xffffffffu, inb);
                if (inb) {
                    int pos = sc + __popc(mk & ltm);
                    if (pos < SUBCAP) sbuf[warp][pos] = x;
                }
                sc += __popc(mk);
            }
            elo = wsumi(elo);
            __syncwarp();
            int basr = cl + elo;
            if (sc <= SUBCAP && basr <= rmin && rmax < basr + sc) {
                float aa = (lane < sc) ? sbuf[warp][lane] : INFINITY;
                float bb = (lane + 32 < sc) ? sbuf[warp][lane + 32] : INFINITY;
                bitonic64(aa, bb, lane);
                ql[w] = sorted_at(aa, bb, rmin - basr);
                qh[w] = sorted_at(aa, bb, rmax - basr);
            } else {
                select2c(bw, g, rmin - cl, rmax - cl, lane, &ql[w], &qh[w]);
            }
            __syncwarp();
        } else {
            ql[w] = slow_rank(v, base0, rg, rmin);
            qh[w] = (rmax == rmin) ? ql[w] : slow_rank(v, base0, rg, rmax);
        }
    }

    if (lane == 0) {
        const double n = (double)NPP;
        double s1 = S1, s2 = S2, s3 = S3, s4 = S4;
        double mean = s1 / n;
        double c2m = s2 - n * mean * mean;
        double c3m = s3 - 3.0 * mean * s2 + 2.0 * n * mean * mean * mean;
        double m2s = mean * mean;
        double c4m = s4 - 4.0 * mean * s3 + 6.0 * m2s * s2 - 3.0 * n * m2s * m2s;
        double sd = sqrt(c2m / (n - 1.0));
        double sde = sd + 1e-8;
        double energy = s2 / n;
        double rms = sqrt(energy + 1e-8);
        double i3 = 1.0 / (sde * sde * sde);
        double skew = (c3m / n) * i3;
        double kurt = (c4m / n) * i3 / sde - 3.0;
        float q25 = ql[0] * 0.25f + qh[0] * 0.75f;
        float q75 = ql[2] * 0.75f + qh[2] * 0.25f;

        float* o = out + (size_t)p * 10;
        o[0] = (float)mean; o[1] = (float)sd; o[2] = mn; o[3] = mx;
        o[4] = (float)energy; o[5] = (float)rms; o[6] = (float)skew;
        o[7] = (float)kurt; o[8] = ql[1]; o[9] = q75 - q25;
    }
}

__device__ __forceinline__ int tau_t(int t) {
    int c = 0;
    if (t + 1 < TT) c++;
    if (t - 1 >= 0) c++;
    if (t + 2 < TT) c++;
    if (t - 2 >= 0) c++;
    return c;
}

__global__ void edge_kernel(float* __restrict__ out)
{
    int node = blockIdx.x * blockDim.x + threadIdx.x;
    if (node >= NODES) return;
    int t = node / NPF;
    int rem = node % NPF;
    int i = rem / GW;
    int j = rem % GW;

    int mt = t < 30 ? t : 30;
    int cum_tau = (t > 0 ? 2 : 0) + (t > 1 ? 3 : 0)
                + 4 * (mt > 2 ? (mt - 2) : 0) + (t > 30 ? 3 : 0);
    int taut = tau_t(t);
    int rowpref = (i == 0) ? 0 : (31 + 50 * (i - 1));
    int ci = (i == 0 || i == GH - 1) ? 2 : 3;
    int cumcj = (j > 0 ? 2 : 0) + 3 * (j > 1 ? (j - 1) : 0);
    int sp = rowpref + ci * cumcj - j;
    int off = 312 * t + 49 * cum_tau + sp + rem * taut;

    const int di[8] = {-1,-1,-1, 0, 0, 1, 1, 1};
    const int dj[8] = {-1, 0, 1,-1, 1,-1, 0, 1};
    int e = off;
    float fnode = (float)node;
    #pragma unroll
    for (int q = 0; q < 8; q++) {
        int ni = i + di[q], nj = j + dj[q];
        if (ni >= 0 && ni < GH && nj >= 0 && nj < GW) {
            out[e]         = fnode;
            out[NEDGE + e] = (float)(t * NPF + ni * GW + nj);
            e++;
        }
    }
    const int dts[4] = {1, -1, 2, -2};
    #pragma unroll
    for (int q = 0; q < 4; q++) {
        int tt2 = t + dts[q];
        if (tt2 >= 0 && tt2 < TT) {
            out[e]         = fnode;
            out[NEDGE + e] = (float)(tt2 * NPF + i * GW + j);
            e++;
        }
    }
}

extern "C" void kernel_launch(void* const* d_in, const int* in_sizes, int n_in,
                              void* d_out, int out_size)
{
    const float* video = (const float*)d_in[0];
    float* out = (float*)d_out;

    if (out_size >= XFLOATS + 2 * NEDGE) {
        edge_kernel<<<(NODES + 255) / 256, 256>>>(out + XFLOATS);
    }
    feat_kernel<<<NPATCH / PPB, 32 * PPB>>>(video, out);
}